// round 9
// baseline (speedup 1.0000x reference)
#include <cuda_runtime.h>

#define BB 4
#define SS 2048
#define HH 16
#define NPAIR 64
#define NB 512                 // 64 pairs x 8 tile-groups
#define NTHR 256
#define L2E 1.44269504088896340736f

// Scratch (device globals; no allocation allowed).
__device__ float g_o[BB*SS*HH];    // attn out, [b][s][h]

__device__ __forceinline__ float ex2f(float x) {
    float r; asm("ex2.approx.ftz.f32 %0, %1;" : "=f"(r) : "f"(x)); return r;
}

// ---------------------------------------------------------------------------
// Kernel 1: fused qkv + causal attention.
// Block = (pair=(b,h), tg). Computes k,v[h] for prefix [0, heavy_end) directly
// from x into smem (block-redundant recompute; weights are block-uniform).
// Warps 0-3 handle query tile (15-tg), warps 4-7 handle tile tg -> every
// block has identical total exp work (15*128 prefix rows per 256 queries).
// ---------------------------------------------------------------------------
__global__ void __launch_bounds__(NTHR) attn_kernel(
    const float* __restrict__ x,   // [8192, 16]
    const float* __restrict__ wq,  // [16, 48]
    const float* __restrict__ bq)  // [48]
{
    __shared__ float2 skv[SS];     // 16 KB max (only heavy_end used)

    int t    = threadIdx.x;
    int bx   = blockIdx.x;
    int pair = bx & (NPAIR - 1);
    int tg   = bx >> 6;                       // 0..7
    int b    = pair >> 4, h = pair & 15;
    int heavy_end = (16 - tg) << 7;           // prefix length needed

    const float* xb = x + b * SS * 16;

    // Preload this block's weight columns (uniform across block).
    float wk[16], wv[16], wqc[16];
    #pragma unroll
    for (int d = 0; d < 16; ++d) {
        wqc[d] = wq[d * 48 + h];
        wk[d]  = wq[d * 48 + h + 16];
        wv[d]  = wq[d * 48 + h + 32];
    }
    float bqv = bq[h], bkv = bq[h + 16], bvv = bq[h + 32];

    // Stage k,v for positions [0, heavy_end) into smem (computed from x).
    for (int j = t; j < heavy_end; j += NTHR) {
        const float4* xr = reinterpret_cast<const float4*>(xb + j * 16);
        float4 x0 = xr[0], x1 = xr[1], x2 = xr[2], x3 = xr[3];
        float xv[16] = { x0.x, x0.y, x0.z, x0.w, x1.x, x1.y, x1.z, x1.w,
                         x2.x, x2.y, x2.z, x2.w, x3.x, x3.y, x3.z, x3.w };
        float ak = bkv, av = bvv;
        #pragma unroll
        for (int d = 0; d < 16; ++d) {
            ak = fmaf(xv[d], wk[d], ak);
            av = fmaf(xv[d], wv[d], av);
        }
        skv[j] = make_float2(ak, av);
    }

    // This thread's query (computed directly from x).
    int sub  = t >> 7;                        // 0 = heavy half, 1 = light half
    int tile = sub ? tg : (15 - tg);
    int i    = (tile << 7) + (t & 127);       // query index
    float qi;
    {
        const float4* xr = reinterpret_cast<const float4*>(xb + i * 16);
        float4 x0 = xr[0], x1 = xr[1], x2 = xr[2], x3 = xr[3];
        float xv[16] = { x0.x, x0.y, x0.z, x0.w, x1.x, x1.y, x1.z, x1.w,
                         x2.x, x2.y, x2.z, x2.w, x3.x, x3.y, x3.z, x3.w };
        float aq = bqv;
        #pragma unroll
        for (int d = 0; d < 16; ++d) aq = fmaf(xv[d], wqc[d], aq);
        qi = aq * L2E;                        // scale=1, fold log2(e)
    }
    __syncthreads();

    // Causal softmax-weighted sum over j in [0, i].
    float den0 = 0.f, den1 = 0.f, num0 = 0.f, num1 = 0.f;
    int j = 0;
    #pragma unroll 4
    for (; j < i; j += 2) {                   // j, j+1 both <= i
        float2 a = skv[j];
        float2 c = skv[j + 1];
        float e0 = ex2f(qi * a.x);
        float e1 = ex2f(qi * c.x);
        den0 += e0;  num0 = fmaf(e0, a.y, num0);
        den1 += e1;  num1 = fmaf(e1, c.y, num1);
    }
    if (j == i) {                             // diagonal when i even
        float2 a = skv[j];
        float e = ex2f(qi * a.x);
        den0 += e;  num0 = fmaf(e, a.y, num0);
    }

    g_o[(b * SS + i) * HH + h] = (num0 + num1) / (den0 + den1);
}

// ---------------------------------------------------------------------------
// Kernel 2: output projection. Block = 16 rows (256 elements), smem-staged.
// ---------------------------------------------------------------------------
__global__ void __launch_bounds__(NTHR) proj_kernel(
    const float* __restrict__ wo,  // [16, 16]
    const float* __restrict__ bo,  // [16]
    float* __restrict__ out)       // [8192, 16]
{
    __shared__ float so[NTHR];     // 16 rows x 16 cols
    __shared__ float sw[256];
    __shared__ float sb[16];
    int t = threadIdx.x;

    so[t] = g_o[blockIdx.x * NTHR + t];       // coalesced
    sw[t] = wo[t];
    if (t < 16) sb[t] = bo[t];
    __syncthreads();

    int rl = t >> 4, c = t & 15;              // local row, out col
    float acc = sb[c];
    #pragma unroll
    for (int d = 0; d < 16; ++d)
        acc = fmaf(so[rl * 16 + d], sw[d * 16 + c], acc);

    out[blockIdx.x * NTHR + t] = acc;         // coalesced
}

// ---------------------------------------------------------------------------
extern "C" void kernel_launch(void* const* d_in, const int* in_sizes, int n_in,
                              void* d_out, int out_size)
{
    const float* x     = (const float*)d_in[0];
    const float* w_qkv = (const float*)d_in[1];
    const float* b_qkv = (const float*)d_in[2];
    const float* w_out = (const float*)d_in[3];
    const float* b_out = (const float*)d_in[4];
    float* out = (float*)d_out;

    attn_kernel<<<NB, NTHR>>>(x, w_qkv, b_qkv);
    proj_kernel<<<(BB * SS * HH) / NTHR, NTHR>>>(w_out, b_out, out);
}